// round 7
// baseline (speedup 1.0000x reference)
#include <cuda_runtime.h>
#include <cstdint>

typedef unsigned long long ull;

#define TPB   256
#define R_    16
#define D_    1024
#define NWARP 8            // warps per block = column chunks per row
#define MAXROWS 65536

// ---- packed f32x2 helpers ----
__device__ __forceinline__ ull ffma2(ull a, ull b, ull c) {
    ull d;
    asm("fma.rn.f32x2 %0, %1, %2, %3;" : "=l"(d) : "l"(a), "l"(b), "l"(c));
    return d;
}
__device__ __forceinline__ ull fmul2(ull a, ull b) {
    ull d;
    asm("mul.rn.f32x2 %0, %1, %2;" : "=l"(d) : "l"(a), "l"(b));
    return d;
}
__device__ __forceinline__ float lo_(ull v) { return __int_as_float((int)(unsigned)(v & 0xffffffffull)); }
__device__ __forceinline__ float hi_(ull v) { return __int_as_float((int)(unsigned)(v >> 32)); }
__device__ __forceinline__ ull   dup_(float v) {
    ull d;
    asm("mov.b64 %0, {%1, %1};" : "=l"(d) : "r"(__float_as_uint(v)));
    return d;
}
__device__ __forceinline__ ulonglong2 ldg128(const void* p) {
    ulonglong2 v;
    asm("ld.global.nc.v2.u64 {%0, %1}, [%2];" : "=l"(v.x), "=l"(v.y) : "l"(p));
    return v;
}
__device__ __forceinline__ void stcs128(void* p, ull a, ull b) {
    asm volatile("st.global.cs.v2.u64 [%0], {%1, %2};" :: "l"(p), "l"(a), "l"(b));
}

// scratch (static device memory — allowed)
__device__ float4 g_part[MAXROWS * NWARP];   // per (row, warp-chunk): x2, y2, xy
__device__ float2 g_coef[MAXROWS];           // per row: cx, cy

// ---- helper: rank-16 delta for this thread's 4 columns ----
__device__ __forceinline__ void delta4(const float4 b[4], const ulonglong2 a2[R_],
                                       ull& d01, ull& d23)
{
    ull e01, e23;
    {
        ull bb = dup_(b[0].x);
        d01 = fmul2(bb, a2[0].x); d23 = fmul2(bb, a2[0].y);
        bb = dup_(b[0].y);
        e01 = fmul2(bb, a2[1].x); e23 = fmul2(bb, a2[1].y);
        bb = dup_(b[0].z);
        d01 = ffma2(bb, a2[2].x, d01); d23 = ffma2(bb, a2[2].y, d23);
        bb = dup_(b[0].w);
        e01 = ffma2(bb, a2[3].x, e01); e23 = ffma2(bb, a2[3].y, e23);
    }
    #pragma unroll
    for (int q = 1; q < 4; ++q) {
        ull bb = dup_(b[q].x);
        d01 = ffma2(bb, a2[4 * q + 0].x, d01); d23 = ffma2(bb, a2[4 * q + 0].y, d23);
        bb = dup_(b[q].y);
        e01 = ffma2(bb, a2[4 * q + 1].x, e01); e23 = ffma2(bb, a2[4 * q + 1].y, e23);
        bb = dup_(b[q].z);
        d01 = ffma2(bb, a2[4 * q + 2].x, d01); d23 = ffma2(bb, a2[4 * q + 2].y, d23);
        bb = dup_(b[q].w);
        e01 = ffma2(bb, a2[4 * q + 3].x, e01); e23 = ffma2(bb, a2[4 * q + 3].y, e23);
    }
    ull s01, s23;
    asm("add.rn.f32x2 %0, %1, %2;" : "=l"(s01) : "l"(d01), "l"(e01));
    asm("add.rn.f32x2 %0, %1, %2;" : "=l"(s23) : "l"(d23), "l"(e23));
    d01 = s01; d23 = s23;
}

__device__ __forceinline__ void loadB(const float* __restrict__ loraB, int idx, float4 b[4])
{
    if (idx >= 0) {
        const float4* p = reinterpret_cast<const float4*>(loraB + (size_t)idx * R_);
        b[0] = __ldg(p); b[1] = __ldg(p + 1); b[2] = __ldg(p + 2); b[3] = __ldg(p + 3);
    } else {
        b[0] = b[1] = b[2] = b[3] = make_float4(0.f, 0.f, 0.f, 0.f);
    }
}

// ================= Kernel A: partial sums (barrier-free) =================
__global__ __launch_bounds__(TPB, 2)
void kA(const int*   __restrict__ indices,
        const float* __restrict__ baseW,
        const float* __restrict__ loraA,
        const float* __restrict__ loraB,
        int n_rows)
{
    const int tid  = threadIdx.x;
    const int wid  = tid >> 5;
    const int lane = tid & 31;
    const int d0   = tid * 4;

    ulonglong2 a2[R_];
    #pragma unroll
    for (int r = 0; r < R_; ++r) a2[r] = ldg128(loraA + r * D_ + d0);

    const int G = gridDim.x;
    int g = blockIdx.x;

    int idx_c = (g < n_rows) ? __ldg(indices + g) : -1;
    int idx_n = (g + G < n_rows) ? __ldg(indices + g + G) : -1;
    ulonglong2 x_c = (idx_c >= 0) ? ldg128(baseW + (size_t)idx_c * D_ + d0)
                                  : make_ulonglong2(0ull, 0ull);

    for (; g < n_rows; g += G) {
        // pipeline: idx depth-2, x depth-1
        int idx_nn = (g + 2 * G < n_rows) ? __ldg(indices + g + 2 * G) : -1;
        ulonglong2 x_n = (idx_n >= 0) ? ldg128(baseW + (size_t)idx_n * D_ + d0)
                                      : make_ulonglong2(0ull, 0ull);
        float4 b[4];
        loadB(loraB, idx_c, b);

        ull d01, d23;
        delta4(b, a2, d01, d23);

        float x0 = lo_(x_c.x), x1 = hi_(x_c.x), x2c = lo_(x_c.y), x3 = hi_(x_c.y);
        float y0 = lo_(d01),   y1 = hi_(d01),   y2c = lo_(d23),   y3 = hi_(d23);

        // raw delta is 0.1 * (b @ A) — fold SCALING into partials via y*0.1 later?
        // No: keep delta unscaled here; scaling folded in kernel B/C consistently.
        float sx2 = fmaf(x0, x0, fmaf(x1, x1, fmaf(x2c, x2c, x3 * x3)));
        float sy2 = fmaf(y0, y0, fmaf(y1, y1, fmaf(y2c, y2c, y3 * y3)));
        float sxy = fmaf(x0, y0, fmaf(x1, y1, fmaf(x2c, y2c, x3 * y3)));

        #pragma unroll
        for (int off = 16; off > 0; off >>= 1) {
            sx2 += __shfl_xor_sync(0xffffffffu, sx2, off);
            sy2 += __shfl_xor_sync(0xffffffffu, sy2, off);
            sxy += __shfl_xor_sync(0xffffffffu, sxy, off);
        }
        if (lane == 0)
            g_part[(g << 3) | wid] = make_float4(sx2, sy2, sxy, 0.f);

        idx_c = idx_n; idx_n = idx_nn; x_c = x_n;
    }
}

// ================= Kernel B: reduce chunks + epilogue =================
__global__ __launch_bounds__(256)
void kB(int n_rows)
{
    int i = blockIdx.x * blockDim.x + threadIdx.x;
    if (i >= n_rows) return;

    float x2 = 0.f, y2r = 0.f, xyr = 0.f;
    #pragma unroll
    for (int w = 0; w < NWARP; ++w) {
        float4 p = g_part[(i << 3) | w];
        x2 += p.x; y2r += p.y; xyr += p.z;
    }
    // delta = SCALING * (b@A): partials were computed on raw b@A
    const float SC = 0.1f;
    float y2 = y2r * (SC * SC);
    float xy = xyr * SC;

    const float MAXN = 1.0f - 1e-5f;
    const float EPSN = 1e-5f;

    float nx = sqrtf(x2);
    float sx = (nx > MAXN) ? __fdividef(MAXN, fmaxf(nx, EPSN)) : 1.0f;
    float ny = sqrtf(y2);
    float sy = (ny > MAXN) ? __fdividef(MAXN, fmaxf(ny, EPSN)) : 1.0f;

    float X2 = sx * sx * x2;
    float Y2 = sy * sy * y2;
    float XY = sx * sy * xy;

    float A_  = 1.0f + 2.0f * XY + Y2;
    float B_  = 1.0f - X2;
    float den = fmaxf(1.0f + 2.0f * XY + X2 * Y2, 1e-15f);

    float n2 = (A_ * A_ * X2 + 2.0f * A_ * B_ * XY + B_ * B_ * Y2) / (den * den);
    float no = sqrtf(fmaxf(n2, 0.0f));
    float sf = (no > MAXN) ? __fdividef(MAXN, fmaxf(no, EPSN)) : 1.0f;

    float cx = __fdividef(sf * A_ * sx, den);
    float cy = __fdividef(sf * B_ * sy, den) * SC;   // fold SCALING into cy
    g_coef[i] = make_float2(cx, cy);
}

// ================= Kernel C: apply (barrier-free) =================
__global__ __launch_bounds__(TPB, 2)
void kC(const int*   __restrict__ indices,
        const float* __restrict__ baseW,
        const float* __restrict__ loraA,
        const float* __restrict__ loraB,
        float*       __restrict__ out,
        int n_rows)
{
    const int tid = threadIdx.x;
    const int d0  = tid * 4;

    ulonglong2 a2[R_];
    #pragma unroll
    for (int r = 0; r < R_; ++r) a2[r] = ldg128(loraA + r * D_ + d0);

    const int G = gridDim.x;
    int g = blockIdx.x;

    int idx_c = (g < n_rows) ? __ldg(indices + g) : -1;
    int idx_n = (g + G < n_rows) ? __ldg(indices + g + G) : -1;
    ulonglong2 x_c = (idx_c >= 0) ? ldg128(baseW + (size_t)idx_c * D_ + d0)
                                  : make_ulonglong2(0ull, 0ull);

    for (; g < n_rows; g += G) {
        int idx_nn = (g + 2 * G < n_rows) ? __ldg(indices + g + 2 * G) : -1;
        ulonglong2 x_n = (idx_n >= 0) ? ldg128(baseW + (size_t)idx_n * D_ + d0)
                                      : make_ulonglong2(0ull, 0ull);
        float2 cf = __ldg(&g_coef[g]);
        float4 b[4];
        loadB(loraB, idx_c, b);

        ull d01, d23;
        delta4(b, a2, d01, d23);

        ull cxd = dup_(cf.x), cyd = dup_(cf.y);
        ull o01 = ffma2(cxd, x_c.x, fmul2(cyd, d01));
        ull o23 = ffma2(cxd, x_c.y, fmul2(cyd, d23));
        stcs128(out + (size_t)g * D_ + d0, o01, o23);

        idx_c = idx_n; idx_n = idx_nn; x_c = x_n;
    }
}

extern "C" void kernel_launch(void* const* d_in, const int* in_sizes, int n_in,
                              void* d_out, int out_size)
{
    const int*   indices = (const int*)  d_in[0];
    const float* baseW   = (const float*)d_in[1];
    const float* loraA   = (const float*)d_in[2];
    const float* loraB   = (const float*)d_in[3];
    float*       out     = (float*)d_out;

    int n_rows = in_sizes[0];                 // 32768
    int gridAC = 2 * 148;                     // 2 CTAs/SM, persistent grid-stride
    if (gridAC > n_rows) gridAC = n_rows;
    int gridB  = (n_rows + 255) / 256;

    kA<<<gridAC, TPB>>>(indices, baseW, loraA, loraB, n_rows);
    kB<<<gridB, 256>>>(n_rows);
    kC<<<gridAC, TPB>>>(indices, baseW, loraA, loraB, out, n_rows);
}

// round 8
// speedup vs baseline: 1.0244x; 1.0244x over previous
#include <cuda_runtime.h>
#include <cstdint>

typedef unsigned long long ull;

#define TPB   256
#define R_    16
#define D_    1024
#define NWARP 8            // warps per block = column chunks per row
#define MAXROWS 65536

// ---- packed f32x2 helpers ----
__device__ __forceinline__ ull ffma2(ull a, ull b, ull c) {
    ull d;
    asm("fma.rn.f32x2 %0, %1, %2, %3;" : "=l"(d) : "l"(a), "l"(b), "l"(c));
    return d;
}
__device__ __forceinline__ ull fmul2(ull a, ull b) {
    ull d;
    asm("mul.rn.f32x2 %0, %1, %2;" : "=l"(d) : "l"(a), "l"(b));
    return d;
}
__device__ __forceinline__ float lo_(ull v) { return __int_as_float((int)(unsigned)(v & 0xffffffffull)); }
__device__ __forceinline__ float hi_(ull v) { return __int_as_float((int)(unsigned)(v >> 32)); }
__device__ __forceinline__ ull   dup_(float v) {
    ull d;
    asm("mov.b64 %0, {%1, %1};" : "=l"(d) : "r"(__float_as_uint(v)));
    return d;
}
__device__ __forceinline__ ulonglong2 ldg128(const void* p) {
    ulonglong2 v;
    asm("ld.global.nc.v2.u64 {%0, %1}, [%2];" : "=l"(v.x), "=l"(v.y) : "l"(p));
    return v;
}
__device__ __forceinline__ void stcs128(void* p, ull a, ull b) {
    asm volatile("st.global.cs.v2.u64 [%0], {%1, %2};" :: "l"(p), "l"(a), "l"(b));
}

// scratch (static device memory — allowed)
__device__ float4 g_part[MAXROWS * NWARP];   // per (row, warp-chunk): x2, y2, xy
__device__ float2 g_coef[MAXROWS];           // per row: cx, cy

// ---- helper: rank-16 delta for this thread's 4 columns ----
__device__ __forceinline__ void delta4(const float4 b[4], const ulonglong2 a2[R_],
                                       ull& d01, ull& d23)
{
    ull e01, e23;
    {
        ull bb = dup_(b[0].x);
        d01 = fmul2(bb, a2[0].x); d23 = fmul2(bb, a2[0].y);
        bb = dup_(b[0].y);
        e01 = fmul2(bb, a2[1].x); e23 = fmul2(bb, a2[1].y);
        bb = dup_(b[0].z);
        d01 = ffma2(bb, a2[2].x, d01); d23 = ffma2(bb, a2[2].y, d23);
        bb = dup_(b[0].w);
        e01 = ffma2(bb, a2[3].x, e01); e23 = ffma2(bb, a2[3].y, e23);
    }
    #pragma unroll
    for (int q = 1; q < 4; ++q) {
        ull bb = dup_(b[q].x);
        d01 = ffma2(bb, a2[4 * q + 0].x, d01); d23 = ffma2(bb, a2[4 * q + 0].y, d23);
        bb = dup_(b[q].y);
        e01 = ffma2(bb, a2[4 * q + 1].x, e01); e23 = ffma2(bb, a2[4 * q + 1].y, e23);
        bb = dup_(b[q].z);
        d01 = ffma2(bb, a2[4 * q + 2].x, d01); d23 = ffma2(bb, a2[4 * q + 2].y, d23);
        bb = dup_(b[q].w);
        e01 = ffma2(bb, a2[4 * q + 3].x, e01); e23 = ffma2(bb, a2[4 * q + 3].y, e23);
    }
    ull s01, s23;
    asm("add.rn.f32x2 %0, %1, %2;" : "=l"(s01) : "l"(d01), "l"(e01));
    asm("add.rn.f32x2 %0, %1, %2;" : "=l"(s23) : "l"(d23), "l"(e23));
    d01 = s01; d23 = s23;
}

__device__ __forceinline__ void loadB(const float* __restrict__ loraB, int idx, float4 b[4])
{
    if (idx >= 0) {
        const float4* p = reinterpret_cast<const float4*>(loraB + (size_t)idx * R_);
        b[0] = __ldg(p); b[1] = __ldg(p + 1); b[2] = __ldg(p + 2); b[3] = __ldg(p + 3);
    } else {
        b[0] = b[1] = b[2] = b[3] = make_float4(0.f, 0.f, 0.f, 0.f);
    }
}

// ================= Kernel A: partial sums (barrier-free) =================
__global__ __launch_bounds__(TPB, 2)
void kA(const int*   __restrict__ indices,
        const float* __restrict__ baseW,
        const float* __restrict__ loraA,
        const float* __restrict__ loraB,
        int n_rows)
{
    const int tid  = threadIdx.x;
    const int wid  = tid >> 5;
    const int lane = tid & 31;
    const int d0   = tid * 4;

    ulonglong2 a2[R_];
    #pragma unroll
    for (int r = 0; r < R_; ++r) a2[r] = ldg128(loraA + r * D_ + d0);

    const int G = gridDim.x;
    int g = blockIdx.x;

    int idx_c = (g < n_rows) ? __ldg(indices + g) : -1;
    int idx_n = (g + G < n_rows) ? __ldg(indices + g + G) : -1;
    ulonglong2 x_c = (idx_c >= 0) ? ldg128(baseW + (size_t)idx_c * D_ + d0)
                                  : make_ulonglong2(0ull, 0ull);

    for (; g < n_rows; g += G) {
        // pipeline: idx depth-2, x depth-1
        int idx_nn = (g + 2 * G < n_rows) ? __ldg(indices + g + 2 * G) : -1;
        ulonglong2 x_n = (idx_n >= 0) ? ldg128(baseW + (size_t)idx_n * D_ + d0)
                                      : make_ulonglong2(0ull, 0ull);
        float4 b[4];
        loadB(loraB, idx_c, b);

        ull d01, d23;
        delta4(b, a2, d01, d23);

        float x0 = lo_(x_c.x), x1 = hi_(x_c.x), x2c = lo_(x_c.y), x3 = hi_(x_c.y);
        float y0 = lo_(d01),   y1 = hi_(d01),   y2c = lo_(d23),   y3 = hi_(d23);

        // raw delta is 0.1 * (b @ A) — fold SCALING into partials via y*0.1 later?
        // No: keep delta unscaled here; scaling folded in kernel B/C consistently.
        float sx2 = fmaf(x0, x0, fmaf(x1, x1, fmaf(x2c, x2c, x3 * x3)));
        float sy2 = fmaf(y0, y0, fmaf(y1, y1, fmaf(y2c, y2c, y3 * y3)));
        float sxy = fmaf(x0, y0, fmaf(x1, y1, fmaf(x2c, y2c, x3 * y3)));

        #pragma unroll
        for (int off = 16; off > 0; off >>= 1) {
            sx2 += __shfl_xor_sync(0xffffffffu, sx2, off);
            sy2 += __shfl_xor_sync(0xffffffffu, sy2, off);
            sxy += __shfl_xor_sync(0xffffffffu, sxy, off);
        }
        if (lane == 0)
            g_part[(g << 3) | wid] = make_float4(sx2, sy2, sxy, 0.f);

        idx_c = idx_n; idx_n = idx_nn; x_c = x_n;
    }
}

// ================= Kernel B: reduce chunks + epilogue =================
__global__ __launch_bounds__(256)
void kB(int n_rows)
{
    int i = blockIdx.x * blockDim.x + threadIdx.x;
    if (i >= n_rows) return;

    float x2 = 0.f, y2r = 0.f, xyr = 0.f;
    #pragma unroll
    for (int w = 0; w < NWARP; ++w) {
        float4 p = g_part[(i << 3) | w];
        x2 += p.x; y2r += p.y; xyr += p.z;
    }
    // delta = SCALING * (b@A): partials were computed on raw b@A
    const float SC = 0.1f;
    float y2 = y2r * (SC * SC);
    float xy = xyr * SC;

    const float MAXN = 1.0f - 1e-5f;
    const float EPSN = 1e-5f;

    float nx = sqrtf(x2);
    float sx = (nx > MAXN) ? __fdividef(MAXN, fmaxf(nx, EPSN)) : 1.0f;
    float ny = sqrtf(y2);
    float sy = (ny > MAXN) ? __fdividef(MAXN, fmaxf(ny, EPSN)) : 1.0f;

    float X2 = sx * sx * x2;
    float Y2 = sy * sy * y2;
    float XY = sx * sy * xy;

    float A_  = 1.0f + 2.0f * XY + Y2;
    float B_  = 1.0f - X2;
    float den = fmaxf(1.0f + 2.0f * XY + X2 * Y2, 1e-15f);

    float n2 = (A_ * A_ * X2 + 2.0f * A_ * B_ * XY + B_ * B_ * Y2) / (den * den);
    float no = sqrtf(fmaxf(n2, 0.0f));
    float sf = (no > MAXN) ? __fdividef(MAXN, fmaxf(no, EPSN)) : 1.0f;

    float cx = __fdividef(sf * A_ * sx, den);
    float cy = __fdividef(sf * B_ * sy, den) * SC;   // fold SCALING into cy
    g_coef[i] = make_float2(cx, cy);
}

// ================= Kernel C: apply (barrier-free) =================
__global__ __launch_bounds__(TPB, 2)
void kC(const int*   __restrict__ indices,
        const float* __restrict__ baseW,
        const float* __restrict__ loraA,
        const float* __restrict__ loraB,
        float*       __restrict__ out,
        int n_rows)
{
    const int tid = threadIdx.x;
    const int d0  = tid * 4;

    ulonglong2 a2[R_];
    #pragma unroll
    for (int r = 0; r < R_; ++r) a2[r] = ldg128(loraA + r * D_ + d0);

    const int G = gridDim.x;
    int g = blockIdx.x;

    int idx_c = (g < n_rows) ? __ldg(indices + g) : -1;
    int idx_n = (g + G < n_rows) ? __ldg(indices + g + G) : -1;
    ulonglong2 x_c = (idx_c >= 0) ? ldg128(baseW + (size_t)idx_c * D_ + d0)
                                  : make_ulonglong2(0ull, 0ull);

    for (; g < n_rows; g += G) {
        int idx_nn = (g + 2 * G < n_rows) ? __ldg(indices + g + 2 * G) : -1;
        ulonglong2 x_n = (idx_n >= 0) ? ldg128(baseW + (size_t)idx_n * D_ + d0)
                                      : make_ulonglong2(0ull, 0ull);
        float2 cf = __ldg(&g_coef[g]);
        float4 b[4];
        loadB(loraB, idx_c, b);

        ull d01, d23;
        delta4(b, a2, d01, d23);

        ull cxd = dup_(cf.x), cyd = dup_(cf.y);
        ull o01 = ffma2(cxd, x_c.x, fmul2(cyd, d01));
        ull o23 = ffma2(cxd, x_c.y, fmul2(cyd, d23));
        stcs128(out + (size_t)g * D_ + d0, o01, o23);

        idx_c = idx_n; idx_n = idx_nn; x_c = x_n;
    }
}

extern "C" void kernel_launch(void* const* d_in, const int* in_sizes, int n_in,
                              void* d_out, int out_size)
{
    const int*   indices = (const int*)  d_in[0];
    const float* baseW   = (const float*)d_in[1];
    const float* loraA   = (const float*)d_in[2];
    const float* loraB   = (const float*)d_in[3];
    float*       out     = (float*)d_out;

    int n_rows = in_sizes[0];                 // 32768
    int gridAC = 2 * 148;                     // 2 CTAs/SM, persistent grid-stride
    if (gridAC > n_rows) gridAC = n_rows;
    int gridB  = (n_rows + 255) / 256;

    kA<<<gridAC, TPB>>>(indices, baseW, loraA, loraB, n_rows);
    kB<<<gridB, 256>>>(n_rows);
    kC<<<gridAC, TPB>>>(indices, baseW, loraA, loraB, out, n_rows);
}